// round 8
// baseline (speedup 1.0000x reference)
#include <cuda_runtime.h>

#define O_TOTAL 16384

// Scratch: A values pre-multiplied by |W2[h]|, stored as duplicated f32 pairs
// g_Aw2[h*64 + b] = {a, a}
__device__ ulonglong2 g_Aw2[128 * 64 / 2];   // 64KB, 16B-aligned

// ---------- packed f32x2 helpers ----------
__device__ __forceinline__ unsigned long long pack2(float x, float y) {
    unsigned long long u;
    asm("mov.b64 %0, {%1,%2};" : "=l"(u) : "f"(x), "f"(y));
    return u;
}
__device__ __forceinline__ void unpack2(unsigned long long u, float &x, float &y) {
    asm("mov.b64 {%0,%1}, %2;" : "=f"(x), "=f"(y) : "l"(u));
}
__device__ __forceinline__ unsigned long long add2(unsigned long long a, unsigned long long b) {
    unsigned long long d;
    asm("add.rn.f32x2 %0, %1, %2;" : "=l"(d) : "l"(a), "l"(b));
    return d;
}
__device__ __forceinline__ unsigned long long fma2(unsigned long long a, unsigned long long b, unsigned long long c) {
    unsigned long long d;
    asm("fma.rn.f32x2 %0, %1, %2, %3;" : "=l"(d) : "l"(a), "l"(b), "l"(c));
    return d;
}
__device__ __forceinline__ unsigned long long relu2(unsigned long long v) {
    float x, y;
    unpack2(v, x, y);
    x = fmaxf(x, 0.0f);
    y = fmaxf(y, 0.0f);
    return pack2(x, y);
}

// =====================================================================
// Kernel A: 16 CTAs x 512 thr. Each computes pz = relu(z@Wz+bz)
// (redundantly), then its 8 h-rows of Aw[h,b] = (pz@W1_h)[b,h]*|W2[h]|,
// written as duplicated pairs.
// =====================================================================
#define A_SMEM ((2048 + 4096 + 128 + 128 * 65) * 4)   // 58368

__global__ void __launch_bounds__(512) k_A(
    const float* __restrict__ z,  const float* __restrict__ Wz,
    const float* __restrict__ bz, const float* __restrict__ W1,
    const float* __restrict__ W2)
{
    extern __shared__ float sm[];
    float* zsT = sm;                    // [k][b]  32x64
    float* Wzs = sm + 2048;             // [k][h]  32x128
    float* bzs = Wzs + 32 * 128;        // [h]
    float* pzT = bzs + 128;             // [h][b]  pitch 65

    int tid = threadIdx.x;
    int cta = blockIdx.x;               // 0..15

    for (int i = tid; i < 2048; i += 512) {
        int k = i >> 6, b = i & 63;
        zsT[k * 64 + b] = z[b * 32 + k];
    }
    for (int i = tid; i < 32 * 128; i += 512) Wzs[i] = Wz[i];
    if (tid < 128) bzs[tid] = bz[tid];
    __syncthreads();

    // pz phase: thread -> b = tid>>3, 16 h outputs [h0, h0+16)
    {
        int b  = tid >> 3;
        int h0 = (tid & 7) * 16;
        float acc[16];
#pragma unroll
        for (int j = 0; j < 16; j++) acc[j] = bzs[h0 + j];

#pragma unroll 4
        for (int k = 0; k < 32; k++) {
            float zv = zsT[k * 64 + b];
            const float4* wrow = (const float4*)(Wzs + k * 128 + h0);
            float4 w0 = wrow[0], w1 = wrow[1], w2 = wrow[2], w3 = wrow[3];
            acc[0]  += zv * w0.x;  acc[1]  += zv * w0.y;
            acc[2]  += zv * w0.z;  acc[3]  += zv * w0.w;
            acc[4]  += zv * w1.x;  acc[5]  += zv * w1.y;
            acc[6]  += zv * w1.z;  acc[7]  += zv * w1.w;
            acc[8]  += zv * w2.x;  acc[9]  += zv * w2.y;
            acc[10] += zv * w2.z;  acc[11] += zv * w2.w;
            acc[12] += zv * w3.x;  acc[13] += zv * w3.y;
            acc[14] += zv * w3.z;  acc[15] += zv * w3.w;
        }
#pragma unroll
        for (int j = 0; j < 16; j++)
            pzT[(h0 + j) * 65 + b] = fmaxf(acc[j], 0.0f);
    }
    __syncthreads();

    // A phase: h = cta*8 + (tid>>6), b = tid&63
    {
        int h = cta * 8 + (tid >> 6);
        int b = tid & 63;
        float a = 0.0f;
#pragma unroll 8
        for (int k = 0; k < 128; k++)
            a += pzT[k * 65 + b] * W1[k * 128 + h];
        float aw = a * fabsf(W2[h]);
        ((unsigned long long*)g_Aw2)[h * 64 + b] = pack2(aw, aw);
    }
}

// =====================================================================
// Kernel main: 128 CTAs x 512 thr. CTA t: o-tile [t*128, t*128+128).
//  preamble: G[o,h] = (fe@W1_f + fb*W1_b + b1)[o,h] * |W2[h]|  (in smem)
//  main:     out[b,o] = sum_h sgn(W2[h]) * max(Aw[h,b] + G[o,h], 0) + b2
// =====================================================================
// float-offset layout:
//   As2  : 0      .. 16384   (8192 ull dup pairs [h][b])
//   Gs   : 16384  .. 32768   ([h][o] floats)
//   s2   : 32768  .. 33024   (128 ull sign dup pairs)
//   W1b_s: 33024, b1_s: 33152, absw_s: 33280  (end 33408)
// Staging overlay inside As2 region: W1fs [0,4096), fes [4096,8224)
#define MAIN_SMEM (33408 * 4)   // 133632

__global__ void __launch_bounds__(512) k_main(
    const float* __restrict__ fe, const float* __restrict__ fb,
    const float* __restrict__ W1, const float* __restrict__ b1,
    const float* __restrict__ W2, const float* __restrict__ b2,
    float* __restrict__ out)
{
    extern __shared__ float sm[];
    unsigned long long* As2 = (unsigned long long*)sm;
    float* Gs = sm + 16384;
    unsigned long long* s2 = (unsigned long long*)(sm + 32768);
    float* W1b_s  = sm + 33024;
    float* b1_s   = sm + 33152;
    float* absw_s = sm + 33280;
    // staging overlay (inside As2 region)
    float* W1fs = sm;            // [c][h] 32x128
    float* fes  = sm + 4096;     // [c][o] pitch 129

    int tid = threadIdx.x;
    int t = blockIdx.x;

    // ---- stage ----
    for (int i = tid; i < 32 * 128; i += 512) W1fs[i] = W1[128 * 128 + i];
    for (int i = tid; i < 128 * 32; i += 512) {
        int o = i >> 5, c = i & 31;
        fes[c * 129 + o] = fe[(t * 128 + o) * 32 + c];
    }
    if (tid < 128) {
        float w = W2[tid];
        float s = (w >= 0.0f) ? 1.0f : -1.0f;
        s2[tid]     = pack2(s, s);
        W1b_s[tid]  = W1[160 * 128 + tid];
        b1_s[tid]   = b1[tid];
        absw_s[tid] = fabsf(w);
    }
    __syncthreads();

    // ---- G tile GEMM (K=32) ----
    {
        int ol = tid & 127;
        int hc = tid >> 7;            // 0..3 -> 32 h each (16 pairs)
        unsigned long long acc[16];
#pragma unroll
        for (int j = 0; j < 16; j++) acc[j] = 0ull;

#pragma unroll 4
        for (int c = 0; c < 32; c++) {
            float f = fes[c * 129 + ol];
            unsigned long long f2 = pack2(f, f);
            const unsigned long long* wrow =
                (const unsigned long long*)(W1fs + c * 128 + hc * 32);
#pragma unroll
            for (int j = 0; j < 16; j++)
                acc[j] = fma2(f2, wrow[j], acc[j]);
        }

        float fbv = fb[t * 128 + ol];
#pragma unroll
        for (int j = 0; j < 16; j++) {
            int h0 = hc * 32 + 2 * j;
            float ax, ay;
            unpack2(acc[j], ax, ay);
            Gs[h0 * 128 + ol]       = (ax + fbv * W1b_s[h0]     + b1_s[h0])     * absw_s[h0];
            Gs[(h0 + 1) * 128 + ol] = (ay + fbv * W1b_s[h0 + 1] + b1_s[h0 + 1]) * absw_s[h0 + 1];
        }
    }
    __syncthreads();     // staging reads done, Gs complete

    // ---- fill As2 from pre-duplicated global (16B copies) ----
    {
        ulonglong2* dst = (ulonglong2*)As2;
        for (int i = tid; i < 4096; i += 512) dst[i] = g_Aw2[i];
    }
    __syncthreads();

    // ---- main loop: thread tile 4b x 4o ----
    int og = tid & 31;            // o0 = og*4
    int bg = tid >> 5;            // b0 = bg*4
    int o0 = og * 4, b0 = bg * 4;

    const ulonglong2* Av = (const ulonglong2*)As2;   // [h*32 + bg*2 (+1)]
    const ulonglong2* Gv = (const ulonglong2*)Gs;    // [h*32 + og]

    unsigned long long a00 = 0ull, a01 = 0ull, a10 = 0ull, a11 = 0ull;
    unsigned long long a20 = 0ull, a21 = 0ull, a30 = 0ull, a31 = 0ull;

#pragma unroll 8
    for (int h = 0; h < 128; h++) {
        ulonglong2 ap01 = Av[h * 32 + bg * 2];       // {a(b0)},{a(b0+1)} dup
        ulonglong2 ap23 = Av[h * 32 + bg * 2 + 1];   // b0+2, b0+3
        ulonglong2 g    = Gv[h * 32 + og];           // {g0,g1},{g2,g3}
        unsigned long long sp = s2[h];

        unsigned long long v;
        v = relu2(add2(ap01.x, g.x)); a00 = fma2(v, sp, a00);
        v = relu2(add2(ap01.x, g.y)); a01 = fma2(v, sp, a01);
        v = relu2(add2(ap01.y, g.x)); a10 = fma2(v, sp, a10);
        v = relu2(add2(ap01.y, g.y)); a11 = fma2(v, sp, a11);
        v = relu2(add2(ap23.x, g.x)); a20 = fma2(v, sp, a20);
        v = relu2(add2(ap23.x, g.y)); a21 = fma2(v, sp, a21);
        v = relu2(add2(ap23.y, g.x)); a30 = fma2(v, sp, a30);
        v = relu2(add2(ap23.y, g.y)); a31 = fma2(v, sp, a31);
    }

    float b2v = b2[0];
    float4 r;
    unpack2(a00, r.x, r.y); unpack2(a01, r.z, r.w);
    r.x += b2v; r.y += b2v; r.z += b2v; r.w += b2v;
    *(float4*)(out + (b0 + 0) * O_TOTAL + t * 128 + o0) = r;
    unpack2(a10, r.x, r.y); unpack2(a11, r.z, r.w);
    r.x += b2v; r.y += b2v; r.z += b2v; r.w += b2v;
    *(float4*)(out + (b0 + 1) * O_TOTAL + t * 128 + o0) = r;
    unpack2(a20, r.x, r.y); unpack2(a21, r.z, r.w);
    r.x += b2v; r.y += b2v; r.z += b2v; r.w += b2v;
    *(float4*)(out + (b0 + 2) * O_TOTAL + t * 128 + o0) = r;
    unpack2(a30, r.x, r.y); unpack2(a31, r.z, r.w);
    r.x += b2v; r.y += b2v; r.z += b2v; r.w += b2v;
    *(float4*)(out + (b0 + 3) * O_TOTAL + t * 128 + o0) = r;
}

extern "C" void kernel_launch(void* const* d_in, const int* in_sizes, int n_in,
                              void* d_out, int out_size) {
    (void)in_sizes; (void)n_in; (void)out_size;
    const float* z  = (const float*)d_in[0];
    const float* fe = (const float*)d_in[1];
    const float* fb = (const float*)d_in[2];
    const float* Wz = (const float*)d_in[3];
    const float* bz = (const float*)d_in[4];
    const float* W1 = (const float*)d_in[5];
    const float* b1 = (const float*)d_in[6];
    const float* W2 = (const float*)d_in[7];
    const float* b2 = (const float*)d_in[8];
    float* out = (float*)d_out;

    cudaFuncSetAttribute(k_A,    cudaFuncAttributeMaxDynamicSharedMemorySize, A_SMEM);
    cudaFuncSetAttribute(k_main, cudaFuncAttributeMaxDynamicSharedMemorySize, MAIN_SMEM);

    k_A<<<16, 512, A_SMEM>>>(z, Wz, bz, W1, W2);
    k_main<<<128, 512, MAIN_SMEM>>>(fe, fb, W1, b1, W2, b2, out);
}

// round 9
// speedup vs baseline: 1.6617x; 1.6617x over previous
#include <cuda_runtime.h>

#define O_TOTAL 16384

// Scratch: A[h][b] = (pz@W1_h)[b,h] * |W2[h]|, plain floats (32KB)
__device__ float g_Aw[128 * 64];

// ---------- packed f32x2 helpers ----------
__device__ __forceinline__ unsigned long long pack2(float x, float y) {
    unsigned long long u;
    asm("mov.b64 %0, {%1,%2};" : "=l"(u) : "f"(x), "f"(y));
    return u;
}
__device__ __forceinline__ void unpack2(unsigned long long u, float &x, float &y) {
    asm("mov.b64 {%0,%1}, %2;" : "=f"(x), "=f"(y) : "l"(u));
}
__device__ __forceinline__ unsigned long long add2(unsigned long long a, unsigned long long b) {
    unsigned long long d;
    asm("add.rn.f32x2 %0, %1, %2;" : "=l"(d) : "l"(a), "l"(b));
    return d;
}
__device__ __forceinline__ unsigned long long fma2(unsigned long long a, unsigned long long b, unsigned long long c) {
    unsigned long long d;
    asm("fma.rn.f32x2 %0, %1, %2, %3;" : "=l"(d) : "l"(a), "l"(b), "l"(c));
    return d;
}
__device__ __forceinline__ unsigned long long relu2(unsigned long long v) {
    float x, y;
    unpack2(v, x, y);
    x = fmaxf(x, 0.0f);
    y = fmaxf(y, 0.0f);
    return pack2(x, y);
}

// =====================================================================
// Kernel A: 16 CTAs x 512. pz = relu(z@Wz+bz) (redundant per CTA),
// then 8 h-rows of Aw[h,b] = (pz@W1_h)[b,h]*|W2[h]| (plain floats).
// =====================================================================
#define A_SMEM ((2048 + 4096 + 128 + 128 * 65) * 4)   // 58368

__global__ void __launch_bounds__(512) k_A(
    const float* __restrict__ z,  const float* __restrict__ Wz,
    const float* __restrict__ bz, const float* __restrict__ W1,
    const float* __restrict__ W2)
{
    extern __shared__ float sm[];
    float* zs  = sm;                    // [b][k]  64x32 (plain, coalesced load)
    float* Wzs = sm + 2048;             // [k][h]  32x128
    float* bzs = Wzs + 32 * 128;        // [h]
    float* pzT = bzs + 128;             // [h][b]  pitch 65

    int tid = threadIdx.x;
    int cta = blockIdx.x;               // 0..15

    for (int i = tid; i < 2048; i += 512)  zs[i]  = z[i];
    for (int i = tid; i < 4096; i += 512)  Wzs[i] = Wz[i];
    if (tid < 128) bzs[tid] = bz[tid];
    __syncthreads();

    // pz phase: thread -> b = tid>>3, 16 h outputs starting at (tid&7)*16
    {
        int b  = tid >> 3;
        int h0 = (tid & 7) * 16;
        float acc[16];
#pragma unroll
        for (int j = 0; j < 16; j++) acc[j] = bzs[h0 + j];

#pragma unroll 4
        for (int k = 0; k < 32; k++) {
            float zv = zs[b * 32 + k];
            const float4* wrow = (const float4*)(Wzs + k * 128 + h0);
            float4 w0 = wrow[0], w1 = wrow[1], w2 = wrow[2], w3 = wrow[3];
            acc[0]  += zv * w0.x;  acc[1]  += zv * w0.y;
            acc[2]  += zv * w0.z;  acc[3]  += zv * w0.w;
            acc[4]  += zv * w1.x;  acc[5]  += zv * w1.y;
            acc[6]  += zv * w1.z;  acc[7]  += zv * w1.w;
            acc[8]  += zv * w2.x;  acc[9]  += zv * w2.y;
            acc[10] += zv * w2.z;  acc[11] += zv * w2.w;
            acc[12] += zv * w3.x;  acc[13] += zv * w3.y;
            acc[14] += zv * w3.z;  acc[15] += zv * w3.w;
        }
#pragma unroll
        for (int j = 0; j < 16; j++)
            pzT[(h0 + j) * 65 + b] = fmaxf(acc[j], 0.0f);
    }
    __syncthreads();

    // A phase: h = cta*8 + (tid>>6), b = tid&63
    {
        int h = cta * 8 + (tid >> 6);
        int b = tid & 63;
        float a = 0.0f;
#pragma unroll 8
        for (int k = 0; k < 128; k++)
            a += pzT[k * 65 + b] * W1[k * 128 + h];
        g_Aw[h * 64 + b] = a * fabsf(W2[h]);
    }
}

// =====================================================================
// Kernel main: 256 CTAs x 512 thr, 2 CTAs/SM. CTA t: o-tile
// [t*64, t*64+64).  Preamble computes G[h][o] in smem:
//   G = (fe@W1_f + fb*W1_b + b1) * |W2[h]|
// Main loop (b-packed f32x2):
//   out[b,o] = sum_h sgn(W2[h]) * max(A[h,b] + G[h,o], 0) + b2
// =====================================================================
// float-offset smem layout (per CTA, 68096 bytes):
//   As    : [0, 8192)       [h][64] plain floats (32KB)
//   Gs    : [8192, 16384)   [h][64] plain floats (32KB)
//   s2    : [16384, 16640)  128 ull sign dup pairs
//   W1b_s : [16640, 16768)
//   b1_s  : [16768, 16896)
//   absw_s: [16896, 17024)
// Staging overlay inside As: W1fs [0,4096), fes [4096,4096+32*65)
#define MAIN_SMEM (17024 * 4)   // 68096

__global__ void __launch_bounds__(512, 2) k_main(
    const float* __restrict__ fe, const float* __restrict__ fb,
    const float* __restrict__ W1, const float* __restrict__ b1,
    const float* __restrict__ W2, const float* __restrict__ b2,
    float* __restrict__ out)
{
    extern __shared__ float sm[];
    float* As = sm;                                        // [h][64]
    float* Gs = sm + 8192;                                 // [h][64]
    unsigned long long* s2 = (unsigned long long*)(sm + 16384);
    float* W1b_s  = sm + 16640;
    float* b1_s   = sm + 16768;
    float* absw_s = sm + 16896;
    // staging overlay (inside As region)
    float* W1fs = sm;             // [c][h] 32x128
    float* fes  = sm + 4096;      // [c][o] pitch 65, 32x64

    int tid = threadIdx.x;
    int t = blockIdx.x;           // o-tile base = t*64

    // ---- stage ----
    for (int i = tid; i < 4096; i += 512) W1fs[i] = W1[128 * 128 + i];
    for (int i = tid; i < 2048; i += 512) {
        int o = i >> 5, c = i & 31;
        fes[c * 65 + o] = fe[(t * 64 + o) * 32 + c];
    }
    if (tid < 128) {
        float w = W2[tid];
        float s = (w >= 0.0f) ? 1.0f : -1.0f;
        s2[tid]     = pack2(s, s);
        W1b_s[tid]  = W1[160 * 128 + tid];
        b1_s[tid]   = b1[tid];
        absw_s[tid] = fabsf(w);
    }
    __syncthreads();

    // ---- G tile GEMM (64o x 128h x 32c) ----
    {
        int o  = tid & 63;
        int hc = tid >> 6;                 // 0..7 -> 16 h each (8 pairs)
        unsigned long long acc[8];
#pragma unroll
        for (int j = 0; j < 8; j++) acc[j] = 0ull;

#pragma unroll 4
        for (int c = 0; c < 32; c++) {
            float f = fes[c * 65 + o];
            unsigned long long f2 = pack2(f, f);
            const unsigned long long* wrow =
                (const unsigned long long*)(W1fs + c * 128 + hc * 16);
#pragma unroll
            for (int j = 0; j < 8; j++)
                acc[j] = fma2(f2, wrow[j], acc[j]);
        }

        float fbv = fb[t * 64 + o];
#pragma unroll
        for (int j = 0; j < 8; j++) {
            int h0 = hc * 16 + 2 * j;
            float ax, ay;
            unpack2(acc[j], ax, ay);
            Gs[h0 * 64 + o]       = (ax + fbv * W1b_s[h0]     + b1_s[h0])     * absw_s[h0];
            Gs[(h0 + 1) * 64 + o] = (ay + fbv * W1b_s[h0 + 1] + b1_s[h0 + 1]) * absw_s[h0 + 1];
        }
    }
    __syncthreads();    // staging reads done; Gs complete

    // ---- fill As (plain floats) over the staging area ----
    for (int i = tid; i < 2048; i += 512)
        ((float4*)As)[i] = ((const float4*)g_Aw)[i];
    __syncthreads();

    // ---- main loop: thread tile 4b x 2o, lanes packed over b ----
    int og = tid & 31;            // o0 = og*2 (uniform b-group per warp)
    int bg = tid >> 5;            // b0 = bg*4
    int o0 = og * 2, b0 = bg * 4;

    const ulonglong2* Av = (const ulonglong2*)As;             // [h*16 + bg] -> {a0,a1},{a2,a3}
    const unsigned long long* Gv = (const unsigned long long*)Gs;  // [h*32 + og] -> {g0,g1}

    unsigned long long acc00 = 0ull, acc01 = 0ull, acc10 = 0ull, acc11 = 0ull;

#pragma unroll 4
    for (int h = 0; h < 128; h++) {
        ulonglong2 ap = Av[h * 16 + bg];       // broadcast within warp
        unsigned long long gp = Gv[h * 32 + og];
        unsigned long long sp = s2[h];         // broadcast

        float glo, ghi;
        unpack2(gp, glo, ghi);
        unsigned long long gd0 = pack2(glo, glo);
        unsigned long long gd1 = pack2(ghi, ghi);

        unsigned long long v;
        v = relu2(add2(ap.x, gd0)); acc00 = fma2(v, sp, acc00);  // {b0,b1} @ o0
        v = relu2(add2(ap.x, gd1)); acc01 = fma2(v, sp, acc01);  // {b0,b1} @ o1
        v = relu2(add2(ap.y, gd0)); acc10 = fma2(v, sp, acc10);  // {b2,b3} @ o0
        v = relu2(add2(ap.y, gd1)); acc11 = fma2(v, sp, acc11);  // {b2,b3} @ o1
    }

    float b2v = b2[0];
    float* obase = out + t * 64 + o0;
    float x0, x1, y0, y1;
    unpack2(acc00, x0, x1);   // (b0,o0),(b1,o0)
    unpack2(acc01, y0, y1);   // (b0,o1),(b1,o1)
    *(float2*)(obase + (b0 + 0) * O_TOTAL) = make_float2(x0 + b2v, y0 + b2v);
    *(float2*)(obase + (b0 + 1) * O_TOTAL) = make_float2(x1 + b2v, y1 + b2v);
    unpack2(acc10, x0, x1);   // (b2,o0),(b3,o0)
    unpack2(acc11, y0, y1);   // (b2,o1),(b3,o1)
    *(float2*)(obase + (b0 + 2) * O_TOTAL) = make_float2(x0 + b2v, y0 + b2v);
    *(float2*)(obase + (b0 + 3) * O_TOTAL) = make_float2(x1 + b2v, y1 + b2v);
}

extern "C" void kernel_launch(void* const* d_in, const int* in_sizes, int n_in,
                              void* d_out, int out_size) {
    (void)in_sizes; (void)n_in; (void)out_size;
    const float* z  = (const float*)d_in[0];
    const float* fe = (const float*)d_in[1];
    const float* fb = (const float*)d_in[2];
    const float* Wz = (const float*)d_in[3];
    const float* bz = (const float*)d_in[4];
    const float* W1 = (const float*)d_in[5];
    const float* b1 = (const float*)d_in[6];
    const float* W2 = (const float*)d_in[7];
    const float* b2 = (const float*)d_in[8];
    float* out = (float*)d_out;

    cudaFuncSetAttribute(k_A,    cudaFuncAttributeMaxDynamicSharedMemorySize, A_SMEM);
    cudaFuncSetAttribute(k_main, cudaFuncAttributeMaxDynamicSharedMemorySize, MAIN_SMEM);

    k_A<<<16, 512, A_SMEM>>>(z, Wz, bz, W1, W2);
    k_main<<<256, 512, MAIN_SMEM>>>(fe, fb, W1, b1, W2, b2, out);
}